// round 15
// baseline (speedup 1.0000x reference)
#include <cuda_runtime.h>
#include <cuda_fp16.h>
#include <cstdint>
#include <math.h>

#define T_TOK 4096
#define DM 512
#define DFF 2048
#define NE 16
#define PP 128
#define N3P 384
#define OUT_ELEMS (T_TOK * DM)
#define BK 32

// ---- rgemm stage (BM=64) ----
#define R_ALO 5120
#define R_OFFB 10240
#define R_BPL 8704
#define R_STAGE 27648
#define R_DYN (2 * R_STAGE)
// ---- expert stage BK=64 ----
#define E_OFFB 18432
#define E_STAGE 35840
#define E_DYN (2 * E_STAGE)
#define EBK 64
// down split-K
#define KSPLIT 2
#define KSEG (DFF / KSPLIT)   // 1024
#define ROWS2 (T_TOK * 2)

// ---------------- device scratch ----------------
__device__ float g_gx[T_TOK * N3P];
__device__ float g_gh[T_TOK * N3P];
__device__ float g_bc[N3P];
__device__ __half g_xh0[T_TOK * DM];
__device__ __half g_xh1[T_TOK * DM];
__device__ __half g_hh0[T_TOK * PP];
__device__ __half g_hh1[T_TOK * PP];
__device__ __half g_wcT0[DM * N3P];
__device__ __half g_wcT1[DM * N3P];
__device__ __half g_whT0[PP * N3P];
__device__ __half g_whT1[PP * N3P];
__device__ __half g_w1h[(size_t)NE * DM * DFF];
__device__ __half g_w2h[(size_t)NE * DFF * DM];
__device__ __half g_hid0[(size_t)ROWS2 * DFF];
__device__ float g_part[(size_t)KSPLIT * ROWS2 * DM];
__device__ int   g_list[NE * T_TOK];
__device__ float g_wt[NE * T_TOK];
__device__ int4  g_slot[T_TOK];
__device__ int   g_count[NE];

// ---------------- helpers ----------------
__device__ __forceinline__ uint32_t smem_u32(const void* p) {
    uint32_t a;
    asm("{ .reg .u64 t; cvta.to.shared.u64 t, %1; cvt.u32.u64 %0, t; }"
        : "=r"(a) : "l"(p));
    return a;
}
__device__ __forceinline__ void ldmx4(uint32_t addr, uint32_t* r) {
    asm volatile("ldmatrix.sync.aligned.m8n8.x4.shared.b16 {%0,%1,%2,%3}, [%4];"
                 : "=r"(r[0]), "=r"(r[1]), "=r"(r[2]), "=r"(r[3]) : "r"(addr));
}
__device__ __forceinline__ void ldmx4t(uint32_t addr, uint32_t* r) {
    asm volatile("ldmatrix.sync.aligned.m8n8.x4.trans.shared.b16 {%0,%1,%2,%3}, [%4];"
                 : "=r"(r[0]), "=r"(r[1]), "=r"(r[2]), "=r"(r[3]) : "r"(addr));
}
__device__ __forceinline__ void mmah(float* d, const uint32_t* a, const uint32_t* b) {
    asm volatile(
        "mma.sync.aligned.m16n8k16.row.col.f32.f16.f16.f32 "
        "{%0,%1,%2,%3}, {%4,%5,%6,%7}, {%8,%9}, {%0,%1,%2,%3};"
        : "+f"(d[0]), "+f"(d[1]), "+f"(d[2]), "+f"(d[3])
        : "r"(a[0]), "r"(a[1]), "r"(a[2]), "r"(a[3]), "r"(b[0]), "r"(b[1]));
}
__device__ __forceinline__ void cp16(uint32_t dst, const void* src, bool ok) {
    int sz = ok ? 16 : 0;
    asm volatile("cp.async.cg.shared.global [%0], [%1], 16, %2;"
                 :: "r"(dst), "l"(src), "r"(sz) : "memory");
}
#define CP_COMMIT() asm volatile("cp.async.commit_group;" ::: "memory")
template <int N>
__device__ __forceinline__ void cp_wait() {
    asm volatile("cp.async.wait_group %0;" :: "n"(N) : "memory");
}
__device__ __forceinline__ uint32_t packh2(float a, float b) {
    __half2 h = __floats2half2_rn(a, b);
    return *reinterpret_cast<uint32_t*>(&h);
}
__device__ __forceinline__ uint32_t packh2_hi(float a, float b, float& ra, float& rb) {
    __half2 h = __floats2half2_rn(a, b);
    ra = a - __low2float(h);
    rb = b - __high2float(h);
    return *reinterpret_cast<uint32_t*>(&h);
}

// ---------------- prep (small): x/h split, fold, transposes, counts -------------
__global__ void __launch_bounds__(256) k_prep_s(
    const float* __restrict__ x, const float* __restrict__ h_prev,
    const float* __restrict__ W_ih, const float* __restrict__ b_ih,
    const float* __restrict__ Wp, const float* __restrict__ bp,
    const float* __restrict__ W_hh)
{
    const int tid = blockIdx.x * blockDim.x + threadIdx.x;
    const int nth = gridDim.x * blockDim.x;
    if (tid < NE) g_count[tid] = 0;

    {
        const float4* s = (const float4*)x;
        uint2* p0 = (uint2*)g_xh0; uint2* p1 = (uint2*)g_xh1;
        for (int i = tid; i < T_TOK * DM / 4; i += nth) {
            float4 v = s[i]; float r0, r1, r2, r3; uint2 H, L;
            H.x = packh2_hi(v.x, v.y, r0, r1); H.y = packh2_hi(v.z, v.w, r2, r3);
            L.x = packh2(r0, r1); L.y = packh2(r2, r3);
            p0[i] = H; p1[i] = L;
        }
    }
    {
        const float4* s = (const float4*)h_prev;
        uint2* p0 = (uint2*)g_hh0; uint2* p1 = (uint2*)g_hh1;
        for (int i = tid; i < T_TOK * PP / 4; i += nth) {
            float4 v = s[i]; float r0, r1, r2, r3; uint2 H, L;
            H.x = packh2_hi(v.x, v.y, r0, r1); H.y = packh2_hi(v.z, v.w, r2, r3);
            L.x = packh2(r0, r1); L.y = packh2(r2, r3);
            p0[i] = H; p1[i] = L;
        }
    }
    for (int i = tid; i < PP * N3P; i += nth) {
        int n = i % N3P, k = i / N3P;
        float v = W_hh[n * PP + k];
        __half h = __float2half_rn(v);
        g_whT0[i] = h;
        g_whT1[i] = __float2half_rn(v - __half2float(h));
    }
    for (int i = tid; i < DM * N3P; i += nth) {
        int n = i % N3P, k = i / N3P;
        float s = 0.f;
        const float* wr = W_ih + n * PP;
#pragma unroll 8
        for (int p = 0; p < PP; p++) s = fmaf(wr[p], Wp[p * DM + k], s);
        __half h = __float2half_rn(s);
        g_wcT0[i] = h;
        g_wcT1[i] = __float2half_rn(s - __half2float(h));
    }
    for (int i = tid; i < N3P; i += nth) {
        float s = b_ih[i];
        const float* wr = W_ih + i * PP;
        for (int p = 0; p < PP; p++) s = fmaf(wr[p], bp[p], s);
        g_bc[i] = s;
    }
}

// ============== expert compute body ==============
__device__ __forceinline__ void chunk1h64(uint32_t sb, int mw, int nw, int lane,
                                          float acc[2][8][4]) {
#pragma unroll
    for (int ks = 0; ks < 4; ks++) {
        uint32_t ah[2][4];
        uint32_t arow = (uint32_t)((mw + (lane & 15)) * 144 + ks * 32 + ((lane >> 4) << 4));
        ldmx4(sb + arow, ah[0]);
        ldmx4(sb + arow + 16 * 144, ah[1]);
        uint32_t brow = (uint32_t)((ks * 16 + (lane & 15)) * 272 + (nw + ((lane >> 4) << 3)) * 2);
#pragma unroll
        for (int nb = 0; nb < 4; nb++) {
            uint32_t bh[4];
            ldmx4t(sb + E_OFFB + brow + nb * 32, bh);
#pragma unroll
            for (int mt = 0; mt < 2; mt++) {
                mmah(acc[mt][2 * nb],     ah[mt], bh);
                mmah(acc[mt][2 * nb + 1], ah[mt], bh + 2);
            }
        }
    }
}

// ============== fused: gate GEMMs (z<2) + W1/W2 conversion (z==2) ==============
__global__ void __launch_bounds__(256) k_rgemm(
    const float* __restrict__ b_hh,
    const float* __restrict__ W1, const float* __restrict__ W2)
{
    const int z = blockIdx.z;
    if (z == 2) {
        // ---- weight conversion plane: 192 CTAs, grid-stride ----
        const int tid = (blockIdx.y * 3 + blockIdx.x) * 256 + threadIdx.x;
        const int nth = 192 * 256;
        {
            const float4* s = (const float4*)W1;
            uint2* p = (uint2*)g_w1h;
            const int n4 = NE * DM * DFF / 4;
            for (int i = tid * 2; i < n4; i += nth * 2) {
                float4 v0 = s[i], v1 = s[i + 1];
                uint2 H0, H1;
                H0.x = packh2(v0.x, v0.y); H0.y = packh2(v0.z, v0.w);
                H1.x = packh2(v1.x, v1.y); H1.y = packh2(v1.z, v1.w);
                p[i] = H0; p[i + 1] = H1;
            }
        }
        {
            const float4* s = (const float4*)W2;
            uint2* p = (uint2*)g_w2h;
            const int n4 = NE * DFF * DM / 4;
            for (int i = tid * 2; i < n4; i += nth * 2) {
                float4 v0 = s[i], v1 = s[i + 1];
                uint2 H0, H1;
                H0.x = packh2(v0.x, v0.y); H0.y = packh2(v0.z, v0.w);
                H1.x = packh2(v1.x, v1.y); H1.y = packh2(v1.z, v1.w);
                p[i] = H0; p[i + 1] = H1;
            }
        }
        return;
    }

    const int K = z ? PP : DM;
    const __half* A0 = z ? g_hh0 : g_xh0;
    const __half* A1 = z ? g_hh1 : g_xh1;
    const __half* B0 = z ? g_whT0 : g_wcT0;
    const __half* B1 = z ? g_whT1 : g_wcT1;
    const float* bias = z ? b_hh : g_bc;
    float* C = z ? g_gh : g_gx;

    const int m0 = blockIdx.y * 64;
    const int n0 = blockIdx.x * 128;
    extern __shared__ __align__(16) char dsm[];
    const uint32_t smb = smem_u32(dsm);

    const int tid = threadIdx.x;
    const int wid = tid >> 5, lane = tid & 31;
    const int mw = (wid & 1) * 32, nw = (wid >> 1) * 32;

    const int ra = tid >> 2, qa = tid & 3;
    const __half* srcA = A0 + (size_t)(m0 + ra) * K + qa * 8;
    const uint32_t dstA = (uint32_t)(ra * 80 + qa * 16);
    const __half* srcB[2];
    uint32_t dstB[2];
#pragma unroll
    for (int i = 0; i < 2; i++) {
        int it = tid + i * 256;
        int k = it >> 4, c = it & 15;
        srcB[i] = B0 + (size_t)k * N3P + n0 + c * 8;
        dstB[i] = (uint32_t)(k * 272 + c * 16);
    }
    const ptrdiff_t dA1 = A1 - A0, dB1 = B1 - B0;

    float acc[2][4][4];
#pragma unroll
    for (int a = 0; a < 2; a++)
#pragma unroll
        for (int b = 0; b < 4; b++)
#pragma unroll
            for (int c = 0; c < 4; c++) acc[a][b][c] = 0.f;

    cp16(smb + dstA, srcA, true);
    cp16(smb + R_ALO + dstA, srcA + dA1, true);
#pragma unroll
    for (int i = 0; i < 2; i++) {
        cp16(smb + R_OFFB + dstB[i], srcB[i], true);
        cp16(smb + R_OFFB + R_BPL + dstB[i], srcB[i] + dB1, true);
    }
    CP_COMMIT();

    const int NK = K / BK;
    for (int c = 0; c < NK; c++) {
        const int s = c & 1;
        cp_wait<0>();
        __syncthreads();
        if (c + 1 < NK) {
            const uint32_t nb = smb + (s ^ 1) * R_STAGE;
            const int kc = (c + 1) * BK;
            cp16(nb + dstA, srcA + kc, true);
            cp16(nb + R_ALO + dstA, srcA + dA1 + kc, true);
#pragma unroll
            for (int i = 0; i < 2; i++) {
                cp16(nb + R_OFFB + dstB[i], srcB[i] + (size_t)kc * N3P, true);
                cp16(nb + R_OFFB + R_BPL + dstB[i], srcB[i] + dB1 + (size_t)kc * N3P, true);
            }
            CP_COMMIT();
        }
        const uint32_t sb = smb + s * R_STAGE;
#pragma unroll
        for (int ks = 0; ks < 2; ks++) {
            uint32_t ah[2][4], al[2][4];
            uint32_t arow = (uint32_t)((mw + (lane & 15)) * 80 + ks * 32 + ((lane >> 4) << 4));
            ldmx4(sb + arow, ah[0]);
            ldmx4(sb + arow + 16 * 80, ah[1]);
            ldmx4(sb + R_ALO + arow, al[0]);
            ldmx4(sb + R_ALO + arow + 16 * 80, al[1]);
            uint32_t brow = (uint32_t)((ks * 16 + (lane & 15)) * 272 + (nw + ((lane >> 4) << 3)) * 2);
#pragma unroll
            for (int nb = 0; nb < 2; nb++) {
                uint32_t bh[4], bl[4];
                ldmx4t(sb + R_OFFB + brow + nb * 32, bh);
                ldmx4t(sb + R_OFFB + R_BPL + brow + nb * 32, bl);
#pragma unroll
                for (int mt = 0; mt < 2; mt++) {
                    float* d0 = acc[mt][2 * nb];
                    float* d1 = acc[mt][2 * nb + 1];
                    mmah(d0, ah[mt], bh);
                    mmah(d0, ah[mt], bl);
                    mmah(d0, al[mt], bh);
                    mmah(d1, ah[mt], bh + 2);
                    mmah(d1, ah[mt], bl + 2);
                    mmah(d1, al[mt], bh + 2);
                }
            }
        }
    }

#pragma unroll
    for (int mt = 0; mt < 2; mt++) {
        int lr0 = mw + mt * 16 + (lane >> 2);
        int lr1 = lr0 + 8;
#pragma unroll
        for (int nt = 0; nt < 4; nt++) {
            int c = nw + nt * 8 + (lane & 3) * 2;
            float z0 = __ldg(&bias[n0 + c]), z1 = __ldg(&bias[n0 + c + 1]);
            float2 v0 = make_float2(acc[mt][nt][0] + z0, acc[mt][nt][1] + z1);
            float2 v1 = make_float2(acc[mt][nt][2] + z0, acc[mt][nt][3] + z1);
            *(float2*)&C[(size_t)(m0 + lr0) * N3P + n0 + c] = v0;
            *(float2*)&C[(size_t)(m0 + lr1) * N3P + n0 + c] = v1;
        }
    }
}

// ---------------- GRU + router (top-2) ----------------
__global__ void __launch_bounds__(128) k_gru_route(
    const float* __restrict__ h_prev,
    const float* __restrict__ Wr, const float* __restrict__ br,
    float* __restrict__ h_out)
{
    const int t = blockIdx.x;
    const int j = threadIdx.x;
    __shared__ float hs[PP];
    __shared__ float logit[NE];

    const float* gx = g_gx + (size_t)t * N3P;
    const float* gh = g_gh + (size_t)t * N3P;
    float xr = gx[j], xz = gx[PP + j], xn = gx[2 * PP + j];
    float hr = gh[j], hz = gh[PP + j], hn = gh[2 * PP + j];
    float r = 1.f / (1.f + expf(-(xr + hr)));
    float z = 1.f / (1.f + expf(-(xz + hz)));
    float n = tanhf(xn + r * hn);
    float hp = h_prev[(size_t)t * PP + j];
    float h = (1.f - z) * n + z * hp;
    hs[j] = h;
    h_out[(size_t)t * PP + j] = h;
    __syncthreads();

    const int w = j >> 5, lane = j & 31;
    for (int e = w; e < NE; e += 4) {
        float p = 0.f;
#pragma unroll
        for (int c = 0; c < 4; c++)
            p += Wr[e * PP + lane + 32 * c] * hs[lane + 32 * c];
#pragma unroll
        for (int off = 16; off; off >>= 1) p += __shfl_down_sync(0xffffffffu, p, off);
        if (lane == 0) logit[e] = p + br[e];
    }
    __syncthreads();

    if (j == 0) {
        int e0 = 0, e1 = -1;
        float l0 = logit[0], l1 = -1e30f;
        for (int e = 1; e < NE; e++) {
            float v = logit[e];
            if (v > l0) { l1 = l0; e1 = e0; l0 = v; e0 = e; }
            else if (v > l1) { l1 = v; e1 = e; }
        }
        float p1 = expf(l1 - l0);
        float inv = 1.f / (1.0f + p1);
        float p0 = inv; p1 *= inv;
        int pos0 = atomicAdd(&g_count[e0], 1);
        g_list[e0 * T_TOK + pos0] = t; g_wt[e0 * T_TOK + pos0] = p0;
        int pos1 = atomicAdd(&g_count[e1], 1);
        g_list[e1 * T_TOK + pos1] = t; g_wt[e1 * T_TOK + pos1] = p1;
        g_slot[t] = make_int4(e0, pos0, e1, pos1);
    }
}

__device__ __forceinline__ void expert_base(int e, int& cnt, int& base) {
    base = 0; cnt = 0;
#pragma unroll
    for (int i = 0; i < NE; i++) {
        int c = __ldg(&g_count[i]);
        if (i < e) base += c;
        if (i == e) cnt = c;
    }
}

// ============== expert up-proj ==============
__global__ void __launch_bounds__(256, 2) k_expert_up(const float* __restrict__ b1)
{
    const int e = blockIdx.z;
    int cnt, base;
    expert_base(e, cnt, base);
    const int m0 = blockIdx.x * 128;
    if (m0 >= cnt) return;
    const int n0 = blockIdx.y * 128;
    const float* b1e = b1 + (size_t)e * DFF;
    const size_t rowbase = (size_t)base + m0;

    extern __shared__ __align__(16) char dsm[];
    const uint32_t smb = smem_u32(dsm);
    __shared__ int rowidx[128];

    const int tid = threadIdx.x;
    const int wid = tid >> 5, lane = tid & 31;
    const int mw = (wid & 3) * 32, nw = (wid >> 2) * 64;

    if (tid < 128)
        rowidx[tid] = (m0 + tid < cnt) ? g_list[e * T_TOK + m0 + tid] : -1;
    __syncthreads();

    const __half* srcA[4];
    bool okA[4];
    uint32_t dstA[4];
#pragma unroll
    for (int i = 0; i < 4; i++) {
        int it = tid + i * 256;
        int r = it >> 3, q = it & 7;
        int gr = rowidx[r];
        okA[i] = (gr >= 0);
        srcA[i] = g_xh0 + (size_t)(okA[i] ? gr : 0) * DM + q * 8;
        dstA[i] = (uint32_t)(r * 144 + q * 16);
    }
    const __half* srcB[4];
    uint32_t dstB[4];
#pragma unroll
    for (int i = 0; i < 4; i++) {
        int it = tid + i * 256;
        int k = it >> 4, c = it & 15;
        srcB[i] = g_w1h + (size_t)e * DM * DFF + (size_t)k * DFF + n0 + c * 8;
        dstB[i] = (uint32_t)(k * 272 + c * 16);
    }

    float acc[2][8][4];
#pragma unroll
    for (int x = 0; x < 2; x++)
#pragma unroll
        for (int y = 0; y < 8; y++)
#pragma unroll
            for (int zz = 0; zz < 4; zz++) acc[x][y][zz] = 0.f;

#pragma unroll
    for (int i = 0; i < 4; i++) {
        cp16(smb + dstA[i], srcA[i], okA[i]);
        cp16(smb + E_OFFB + dstB[i], srcB[i], true);
    }
    CP_COMMIT();

    const int NK = DM / EBK;  // 8
    for (int c = 0; c < NK; c++) {
        const int s = c & 1;
        cp_wait<0>();
        __syncthreads();
        if (c + 1 < NK) {
            const uint32_t nb = smb + (s ^ 1) * E_STAGE;
            const int kc = (c + 1) * EBK;
#pragma unroll
            for (int i = 0; i < 4; i++) {
                cp16(nb + dstA[i], srcA[i] + kc, okA[i]);
                cp16(nb + E_OFFB + dstB[i], srcB[i] + (size_t)kc * DFF, true);
            }
            CP_COMMIT();
        }
        chunk1h64(smb + s * E_STAGE, mw, nw, lane, acc);
    }

#pragma unroll
    for (int mt = 0; mt < 2; mt++) {
        int lr0 = mw + mt * 16 + (lane >> 2);
        int lr1 = lr0 + 8;
        bool ok0 = (m0 + lr0 < cnt), ok1 = (m0 + lr1 < cnt);
        size_t row0 = rowbase + lr0, row1 = rowbase + lr1;
#pragma unroll
        for (int nt = 0; nt < 8; nt++) {
            int c = nw + nt * 8 + (lane & 3) * 2;
            float z0 = __ldg(&b1e[n0 + c]), z1 = __ldg(&b1e[n0 + c + 1]);
            if (ok0) {
                float v0 = fmaxf(acc[mt][nt][0] + z0, 0.f);
                float v1 = fmaxf(acc[mt][nt][1] + z1, 0.f);
                *(uint32_t*)(g_hid0 + row0 * DFF + n0 + c) = packh2(v0, v1);
            }
            if (ok1) {
                float v0 = fmaxf(acc[mt][nt][2] + z0, 0.f);
                float v1 = fmaxf(acc[mt][nt][3] + z1, 0.f);
                *(uint32_t*)(g_hid0 + row1 * DFF + n0 + c) = packh2(v0, v1);
            }
        }
    }
}

// ============== expert down-proj: split-K=2, non-atomic partials ==============
__global__ void __launch_bounds__(256, 2) k_expert_down()
{
    const int e = blockIdx.z;
    int cnt, base;
    expert_base(e, cnt, base);
    const int m0 = blockIdx.x * 128;
    if (m0 >= cnt) return;
    const int n0 = (blockIdx.y & 3) * 128;
    const int kz = blockIdx.y >> 2;
    const int kbase = kz * KSEG;
    const size_t rowbase = (size_t)base + m0;
    float* part = g_part + (size_t)kz * ROWS2 * DM;

    extern __shared__ __align__(16) char dsm[];
    const uint32_t smb = smem_u32(dsm);

    const int tid = threadIdx.x;
    const int wid = tid >> 5, lane = tid & 31;
    const int mw = (wid & 3) * 32, nw = (wid >> 2) * 64;

    const __half* srcA[4];
    bool okA[4];
    uint32_t dstA[4];
#pragma unroll
    for (int i = 0; i < 4; i++) {
        int it = tid + i * 256;
        int r = it >> 3, q = it & 7;
        okA[i] = (m0 + r < cnt);
        srcA[i] = g_hid0 + (okA[i] ? (rowbase + r) : 0) * DFF + kbase + q * 8;
        dstA[i] = (uint32_t)(r * 144 + q * 16);
    }
    const __half* srcB[4];
    uint32_t dstB[4];
#pragma unroll
    for (int i = 0; i < 4; i++) {
        int it = tid + i * 256;
        int k = it >> 4, c = it & 15;
        srcB[i] = g_w2h + (size_t)e * DFF * DM + (size_t)(kbase + k) * DM + n0 + c * 8;
        dstB[i] = (uint32_t)(k * 272 + c * 16);
    }

    float acc[2][8][4];
#pragma unroll
    for (int x = 0; x < 2; x++)
#pragma unroll
        for (int y = 0; y < 8; y++)
#pragma unroll
            for (int zz = 0; zz < 4; zz++) acc[x][y][zz] = 0.f;

#pragma unroll
    for (int i = 0; i < 4; i++) {
        cp16(smb + dstA[i], srcA[i], okA[i]);
        cp16(smb + E_OFFB + dstB[i], srcB[i], true);
    }
    CP_COMMIT();

    const int NK = KSEG / EBK;  // 16
    for (int c = 0; c < NK; c++) {
        const int s = c & 1;
        cp_wait<0>();
        __syncthreads();
        if (c + 1 < NK) {
            const uint32_t nb = smb + (s ^ 1) * E_STAGE;
            const int kc = (c + 1) * EBK;
#pragma unroll
            for (int i = 0; i < 4; i++) {
                cp16(nb + dstA[i], srcA[i] + kc, okA[i]);
                cp16(nb + E_OFFB + dstB[i], srcB[i] + (size_t)kc * DM, true);
            }
            CP_COMMIT();
        }
        chunk1h64(smb + s * E_STAGE, mw, nw, lane, acc);
    }

#pragma unroll
    for (int mt = 0; mt < 2; mt++) {
        int lr0 = mw + mt * 16 + (lane >> 2);
        int lr1 = lr0 + 8;
        bool ok0 = (m0 + lr0 < cnt), ok1 = (m0 + lr1 < cnt);
        size_t row0 = rowbase + lr0, row1 = rowbase + lr1;
#pragma unroll
        for (int nt = 0; nt < 8; nt++) {
            int c = nw + nt * 8 + (lane & 3) * 2;
            if (ok0)
                *(float2*)&part[row0 * DM + n0 + c] =
                    make_float2(acc[mt][nt][0], acc[mt][nt][1]);
            if (ok1)
                *(float2*)&part[row1 * DM + n0 + c] =
                    make_float2(acc[mt][nt][2], acc[mt][nt][3]);
        }
    }
}

// ============== combine ==============
__global__ void __launch_bounds__(128) k_combine(
    const float* __restrict__ b2, float* __restrict__ out)
{
    const int t = blockIdx.x;
    const int tid = threadIdx.x;
    __shared__ int sbase[NE];
    __shared__ int4 sslot;
    if (tid < NE) {
        int b = 0;
        for (int i = 0; i < tid; i++) b += __ldg(&g_count[i]);
        sbase[tid] = b;
    }
    if (tid == 0) sslot = g_slot[t];
    __syncthreads();

    const int e0 = sslot.x, pos0 = sslot.y, e1 = sslot.z, pos1 = sslot.w;
    const size_t r0 = (size_t)sbase[e0] + pos0;
    const size_t r1 = (size_t)sbase[e1] + pos1;
    const float w0 = __ldg(&g_wt[e0 * T_TOK + pos0]);
    const float w1 = __ldg(&g_wt[e1 * T_TOK + pos1]);
    const size_t PL = (size_t)ROWS2 * DM;

    const float4* p0a = (const float4*)(g_part + r0 * DM);
    const float4* p0b = (const float4*)(g_part + PL + r0 * DM);
    const float4* p1a = (const float4*)(g_part + r1 * DM);
    const float4* p1b = (const float4*)(g_part + PL + r1 * DM);
    const float4* bz0 = (const float4*)(b2 + (size_t)e0 * DM);
    const float4* bz1 = (const float4*)(b2 + (size_t)e1 * DM);
    float4* o = (float4*)(out + (size_t)t * DM);

    for (int c = tid; c < DM / 4; c += 128) {
        float4 a0 = p0a[c], a1 = p0b[c], z0 = bz0[c];
        float4 d0 = p1a[c], d1 = p1b[c], z1 = bz1[c];
        float4 r;
        r.x = w0 * (a0.x + a1.x + z0.x) + w1 * (d0.x + d1.x + z1.x);
        r.y = w0 * (a0.y + a1.y + z0.y) + w1 * (d0.y + d1.y + z1.y);
        r.z = w0 * (a0.z + a1.z + z0.z) + w1 * (d0.z + d1.z + z1.z);
        r.w = w0 * (a0.w + a1.w + z0.w) + w1 * (d0.w + d1.w + z1.w);
        o[c] = r;
    }
}

// ---------------- host launcher ----------------
extern "C" void kernel_launch(void* const* d_in, const int* in_sizes, int n_in,
                              void* d_out, int out_size) {
    const float* x      = (const float*)d_in[0];
    const float* h_prev = (const float*)d_in[1];
    const float* Wp     = (const float*)d_in[2];
    const float* bp     = (const float*)d_in[3];
    const float* W_ih   = (const float*)d_in[4];
    const float* W_hh   = (const float*)d_in[5];
    const float* b_ih   = (const float*)d_in[6];
    const float* b_hh   = (const float*)d_in[7];
    const float* Wr     = (const float*)d_in[8];
    const float* br     = (const float*)d_in[9];
    const float* W1     = (const float*)d_in[10];
    const float* b1     = (const float*)d_in[11];
    const float* W2     = (const float*)d_in[12];
    const float* b2     = (const float*)d_in[13];

    float* out   = (float*)d_out;
    float* h_out = out + OUT_ELEMS;

    cudaFuncSetAttribute(k_rgemm,
                         cudaFuncAttributeMaxDynamicSharedMemorySize, R_DYN);
    cudaFuncSetAttribute(k_expert_up,
                         cudaFuncAttributeMaxDynamicSharedMemorySize, E_DYN);
    cudaFuncSetAttribute(k_expert_down,
                         cudaFuncAttributeMaxDynamicSharedMemorySize, E_DYN);

    k_prep_s<<<512, 256>>>(x, h_prev, W_ih, b_ih, Wp, bp, W_hh);
    k_rgemm<<<dim3(3, 64, 3), 256, R_DYN>>>(b_hh, W1, W2);
    k_gru_route<<<T_TOK, 128>>>(h_prev, Wr, br, h_out);
    k_expert_up<<<dim3(T_TOK / 128, DFF / 128, NE), 256, E_DYN>>>(b1);
    k_expert_down<<<dim3(T_TOK / 128, (DM / 128) * KSPLIT, NE), 256, E_DYN>>>();
    k_combine<<<T_TOK, 128>>>(b2, out);
}

// round 16
// speedup vs baseline: 1.0511x; 1.0511x over previous
#include <cuda_runtime.h>
#include <cuda_fp16.h>
#include <cstdint>
#include <math.h>

#define T_TOK 4096
#define DM 512
#define DFF 2048
#define NE 16
#define PP 128
#define N3P 384
#define OUT_ELEMS (T_TOK * DM)
#define BK 32

// ---- rgemm stage (BM=64) ----
#define R_ALO 5120
#define R_OFFB 10240
#define R_BPL 8704
#define R_STAGE 27648
#define R_DYN (2 * R_STAGE)
// ---- expert stage BK=64 ----
#define E_OFFB 18432
#define E_STAGE 35840
#define E_DYN (2 * E_STAGE)
#define EBK 64
// down split-K
#define KSPLIT 2
#define KSEG (DFF / KSPLIT)   // 1024
#define ROWS2 (T_TOK * 2)

// ---------------- device scratch ----------------
__device__ float g_gx[T_TOK * N3P];
__device__ float g_gh[T_TOK * N3P];
__device__ float g_bc[N3P];
__device__ __half g_xh0[T_TOK * DM];
__device__ __half g_xh1[T_TOK * DM];
__device__ __half g_hh0[T_TOK * PP];
__device__ __half g_hh1[T_TOK * PP];
__device__ __half g_wcT0[DM * N3P];
__device__ __half g_wcT1[DM * N3P];
__device__ __half g_whT0[PP * N3P];
__device__ __half g_whT1[PP * N3P];
__device__ __half g_w1h[(size_t)NE * DM * DFF];
__device__ __half g_w2h[(size_t)NE * DFF * DM];
__device__ __half g_hid0[(size_t)ROWS2 * DFF];
__device__ float g_part[(size_t)KSPLIT * ROWS2 * DM];
__device__ int   g_list[NE * T_TOK];
__device__ float g_wt[NE * T_TOK];
__device__ int4  g_slot[T_TOK];
__device__ int   g_count[NE];

// ---------------- helpers ----------------
__device__ __forceinline__ uint32_t smem_u32(const void* p) {
    uint32_t a;
    asm("{ .reg .u64 t; cvta.to.shared.u64 t, %1; cvt.u32.u64 %0, t; }"
        : "=r"(a) : "l"(p));
    return a;
}
__device__ __forceinline__ void ldmx4(uint32_t addr, uint32_t* r) {
    asm volatile("ldmatrix.sync.aligned.m8n8.x4.shared.b16 {%0,%1,%2,%3}, [%4];"
                 : "=r"(r[0]), "=r"(r[1]), "=r"(r[2]), "=r"(r[3]) : "r"(addr));
}
__device__ __forceinline__ void ldmx4t(uint32_t addr, uint32_t* r) {
    asm volatile("ldmatrix.sync.aligned.m8n8.x4.trans.shared.b16 {%0,%1,%2,%3}, [%4];"
                 : "=r"(r[0]), "=r"(r[1]), "=r"(r[2]), "=r"(r[3]) : "r"(addr));
}
__device__ __forceinline__ void mmah(float* d, const uint32_t* a, const uint32_t* b) {
    asm volatile(
        "mma.sync.aligned.m16n8k16.row.col.f32.f16.f16.f32 "
        "{%0,%1,%2,%3}, {%4,%5,%6,%7}, {%8,%9}, {%0,%1,%2,%3};"
        : "+f"(d[0]), "+f"(d[1]), "+f"(d[2]), "+f"(d[3])
        : "r"(a[0]), "r"(a[1]), "r"(a[2]), "r"(a[3]), "r"(b[0]), "r"(b[1]));
}
__device__ __forceinline__ void cp16(uint32_t dst, const void* src, bool ok) {
    int sz = ok ? 16 : 0;
    asm volatile("cp.async.cg.shared.global [%0], [%1], 16, %2;"
                 :: "r"(dst), "l"(src), "r"(sz) : "memory");
}
#define CP_COMMIT() asm volatile("cp.async.commit_group;" ::: "memory")
template <int N>
__device__ __forceinline__ void cp_wait() {
    asm volatile("cp.async.wait_group %0;" :: "n"(N) : "memory");
}
__device__ __forceinline__ uint32_t packh2(float a, float b) {
    __half2 h = __floats2half2_rn(a, b);
    return *reinterpret_cast<uint32_t*>(&h);
}
__device__ __forceinline__ uint32_t packh2_hi(float a, float b, float& ra, float& rb) {
    __half2 h = __floats2half2_rn(a, b);
    ra = a - __low2float(h);
    rb = b - __high2float(h);
    return *reinterpret_cast<uint32_t*>(&h);
}

// ---------------- prep: x/h split, fold, transposes, counts (no W conv) ----------
__global__ void __launch_bounds__(256) k_prep(
    const float* __restrict__ x, const float* __restrict__ h_prev,
    const float* __restrict__ W_ih, const float* __restrict__ b_ih,
    const float* __restrict__ Wp, const float* __restrict__ bp,
    const float* __restrict__ W_hh)
{
    const int tid = blockIdx.x * blockDim.x + threadIdx.x;
    const int nth = gridDim.x * blockDim.x;
    if (tid < NE) g_count[tid] = 0;

    {
        const float4* s = (const float4*)x;
        uint2* p0 = (uint2*)g_xh0; uint2* p1 = (uint2*)g_xh1;
        for (int i = tid; i < T_TOK * DM / 4; i += nth) {
            float4 v = s[i]; float r0, r1, r2, r3; uint2 H, L;
            H.x = packh2_hi(v.x, v.y, r0, r1); H.y = packh2_hi(v.z, v.w, r2, r3);
            L.x = packh2(r0, r1); L.y = packh2(r2, r3);
            p0[i] = H; p1[i] = L;
        }
    }
    {
        const float4* s = (const float4*)h_prev;
        uint2* p0 = (uint2*)g_hh0; uint2* p1 = (uint2*)g_hh1;
        for (int i = tid; i < T_TOK * PP / 4; i += nth) {
            float4 v = s[i]; float r0, r1, r2, r3; uint2 H, L;
            H.x = packh2_hi(v.x, v.y, r0, r1); H.y = packh2_hi(v.z, v.w, r2, r3);
            L.x = packh2(r0, r1); L.y = packh2(r2, r3);
            p0[i] = H; p1[i] = L;
        }
    }
    for (int i = tid; i < PP * N3P; i += nth) {
        int n = i % N3P, k = i / N3P;
        float v = W_hh[n * PP + k];
        __half h = __float2half_rn(v);
        g_whT0[i] = h;
        g_whT1[i] = __float2half_rn(v - __half2float(h));
    }
    for (int i = tid; i < DM * N3P; i += nth) {
        int n = i % N3P, k = i / N3P;
        float s = 0.f;
        const float* wr = W_ih + n * PP;
#pragma unroll 8
        for (int p = 0; p < PP; p++) s = fmaf(wr[p], Wp[p * DM + k], s);
        __half h = __float2half_rn(s);
        g_wcT0[i] = h;
        g_wcT1[i] = __float2half_rn(s - __half2float(h));
    }
    for (int i = tid; i < N3P; i += nth) {
        float s = b_ih[i];
        const float* wr = W_ih + i * PP;
        for (int p = 0; p < PP; p++) s = fmaf(wr[p], bp[p], s);
        g_bc[i] = s;
    }
}

// ============== expert compute body ==============
__device__ __forceinline__ void chunk1h64(uint32_t sb, int mw, int nw, int lane,
                                          float acc[2][8][4]) {
#pragma unroll
    for (int ks = 0; ks < 4; ks++) {
        uint32_t ah[2][4];
        uint32_t arow = (uint32_t)((mw + (lane & 15)) * 144 + ks * 32 + ((lane >> 4) << 4));
        ldmx4(sb + arow, ah[0]);
        ldmx4(sb + arow + 16 * 144, ah[1]);
        uint32_t brow = (uint32_t)((ks * 16 + (lane & 15)) * 272 + (nw + ((lane >> 4) << 3)) * 2);
#pragma unroll
        for (int nb = 0; nb < 4; nb++) {
            uint32_t bh[4];
            ldmx4t(sb + E_OFFB + brow + nb * 32, bh);
#pragma unroll
            for (int mt = 0; mt < 2; mt++) {
                mmah(acc[mt][2 * nb],     ah[mt], bh);
                mmah(acc[mt][2 * nb + 1], ah[mt], bh + 2);
            }
        }
    }
}

// ============== fused gate GEMMs: BM=64, 384 CTAs, 1 sync/chunk ==============
__global__ void __launch_bounds__(256) k_rgemm(const float* __restrict__ b_hh)
{
    const int z = blockIdx.z;
    const int K = z ? PP : DM;
    const __half* A0 = z ? g_hh0 : g_xh0;
    const __half* A1 = z ? g_hh1 : g_xh1;
    const __half* B0 = z ? g_whT0 : g_wcT0;
    const __half* B1 = z ? g_whT1 : g_wcT1;
    const float* bias = z ? b_hh : g_bc;
    float* C = z ? g_gh : g_gx;

    const int m0 = blockIdx.y * 64;
    const int n0 = blockIdx.x * 128;
    extern __shared__ __align__(16) char dsm[];
    const uint32_t smb = smem_u32(dsm);

    const int tid = threadIdx.x;
    const int wid = tid >> 5, lane = tid & 31;
    const int mw = (wid & 1) * 32, nw = (wid >> 1) * 32;

    const int ra = tid >> 2, qa = tid & 3;
    const __half* srcA = A0 + (size_t)(m0 + ra) * K + qa * 8;
    const uint32_t dstA = (uint32_t)(ra * 80 + qa * 16);
    const __half* srcB[2];
    uint32_t dstB[2];
#pragma unroll
    for (int i = 0; i < 2; i++) {
        int it = tid + i * 256;
        int k = it >> 4, c = it & 15;
        srcB[i] = B0 + (size_t)k * N3P + n0 + c * 8;
        dstB[i] = (uint32_t)(k * 272 + c * 16);
    }
    const ptrdiff_t dA1 = A1 - A0, dB1 = B1 - B0;

    float acc[2][4][4];
#pragma unroll
    for (int a = 0; a < 2; a++)
#pragma unroll
        for (int b = 0; b < 4; b++)
#pragma unroll
            for (int c = 0; c < 4; c++) acc[a][b][c] = 0.f;

    cp16(smb + dstA, srcA, true);
    cp16(smb + R_ALO + dstA, srcA + dA1, true);
#pragma unroll
    for (int i = 0; i < 2; i++) {
        cp16(smb + R_OFFB + dstB[i], srcB[i], true);
        cp16(smb + R_OFFB + R_BPL + dstB[i], srcB[i] + dB1, true);
    }
    CP_COMMIT();

    const int NK = K / BK;
    for (int c = 0; c < NK; c++) {
        const int s = c & 1;
        cp_wait<0>();
        __syncthreads();
        if (c + 1 < NK) {
            const uint32_t nb = smb + (s ^ 1) * R_STAGE;
            const int kc = (c + 1) * BK;
            cp16(nb + dstA, srcA + kc, true);
            cp16(nb + R_ALO + dstA, srcA + dA1 + kc, true);
#pragma unroll
            for (int i = 0; i < 2; i++) {
                cp16(nb + R_OFFB + dstB[i], srcB[i] + (size_t)kc * N3P, true);
                cp16(nb + R_OFFB + R_BPL + dstB[i], srcB[i] + dB1 + (size_t)kc * N3P, true);
            }
            CP_COMMIT();
        }
        const uint32_t sb = smb + s * R_STAGE;
#pragma unroll
        for (int ks = 0; ks < 2; ks++) {
            uint32_t ah[2][4], al[2][4];
            uint32_t arow = (uint32_t)((mw + (lane & 15)) * 80 + ks * 32 + ((lane >> 4) << 4));
            ldmx4(sb + arow, ah[0]);
            ldmx4(sb + arow + 16 * 80, ah[1]);
            ldmx4(sb + R_ALO + arow, al[0]);
            ldmx4(sb + R_ALO + arow + 16 * 80, al[1]);
            uint32_t brow = (uint32_t)((ks * 16 + (lane & 15)) * 272 + (nw + ((lane >> 4) << 3)) * 2);
#pragma unroll
            for (int nb = 0; nb < 2; nb++) {
                uint32_t bh[4], bl[4];
                ldmx4t(sb + R_OFFB + brow + nb * 32, bh);
                ldmx4t(sb + R_OFFB + R_BPL + brow + nb * 32, bl);
#pragma unroll
                for (int mt = 0; mt < 2; mt++) {
                    float* d0 = acc[mt][2 * nb];
                    float* d1 = acc[mt][2 * nb + 1];
                    mmah(d0, ah[mt], bh);
                    mmah(d0, ah[mt], bl);
                    mmah(d0, al[mt], bh);
                    mmah(d1, ah[mt], bh + 2);
                    mmah(d1, ah[mt], bl + 2);
                    mmah(d1, al[mt], bh + 2);
                }
            }
        }
    }

#pragma unroll
    for (int mt = 0; mt < 2; mt++) {
        int lr0 = mw + mt * 16 + (lane >> 2);
        int lr1 = lr0 + 8;
#pragma unroll
        for (int nt = 0; nt < 4; nt++) {
            int c = nw + nt * 8 + (lane & 3) * 2;
            float z0 = __ldg(&bias[n0 + c]), z1 = __ldg(&bias[n0 + c + 1]);
            float2 v0 = make_float2(acc[mt][nt][0] + z0, acc[mt][nt][1] + z1);
            float2 v1 = make_float2(acc[mt][nt][2] + z0, acc[mt][nt][3] + z1);
            *(float2*)&C[(size_t)(m0 + lr0) * N3P + n0 + c] = v0;
            *(float2*)&C[(size_t)(m0 + lr1) * N3P + n0 + c] = v1;
        }
    }
}

// ---------------- GRU + router (top-2) + W1/W2 conversion tail ----------------
__global__ void __launch_bounds__(128) k_gru_route(
    const float* __restrict__ h_prev,
    const float* __restrict__ Wr, const float* __restrict__ br,
    float* __restrict__ h_out,
    const float* __restrict__ W1, const float* __restrict__ W2)
{
    const int t = blockIdx.x;
    const int j = threadIdx.x;
    __shared__ float hs[PP];
    __shared__ float logit[NE];

    const float* gx = g_gx + (size_t)t * N3P;
    const float* gh = g_gh + (size_t)t * N3P;
    float xr = gx[j], xz = gx[PP + j], xn = gx[2 * PP + j];
    float hr = gh[j], hz = gh[PP + j], hn = gh[2 * PP + j];
    float r = 1.f / (1.f + expf(-(xr + hr)));
    float z = 1.f / (1.f + expf(-(xz + hz)));
    float n = tanhf(xn + r * hn);
    float hp = h_prev[(size_t)t * PP + j];
    float h = (1.f - z) * n + z * hp;
    hs[j] = h;
    h_out[(size_t)t * PP + j] = h;
    __syncthreads();

    const int w = j >> 5, lane = j & 31;
    for (int e = w; e < NE; e += 4) {
        float p = 0.f;
#pragma unroll
        for (int c = 0; c < 4; c++)
            p += Wr[e * PP + lane + 32 * c] * hs[lane + 32 * c];
#pragma unroll
        for (int off = 16; off; off >>= 1) p += __shfl_down_sync(0xffffffffu, p, off);
        if (lane == 0) logit[e] = p + br[e];
    }
    __syncthreads();

    if (j == 0) {
        int e0 = 0, e1 = -1;
        float l0 = logit[0], l1 = -1e30f;
        for (int e = 1; e < NE; e++) {
            float v = logit[e];
            if (v > l0) { l1 = l0; e1 = e0; l0 = v; e0 = e; }
            else if (v > l1) { l1 = v; e1 = e; }
        }
        float p1 = expf(l1 - l0);
        float inv = 1.f / (1.0f + p1);
        float p0 = inv; p1 *= inv;
        int pos0 = atomicAdd(&g_count[e0], 1);
        g_list[e0 * T_TOK + pos0] = t; g_wt[e0 * T_TOK + pos0] = p0;
        int pos1 = atomicAdd(&g_count[e1], 1);
        g_list[e1 * T_TOK + pos1] = t; g_wt[e1 * T_TOK + pos1] = p1;
        g_slot[t] = make_int4(e0, pos0, e1, pos1);
    }

    // ---- conversion tail: W1/W2 fp32 -> fp16 (independent of routing) ----
    const int gtid = t * 128 + j;
    const int gnth = T_TOK * 128;   // 524288 threads
    {
        const float4* s = (const float4*)W1;
        uint2* p = (uint2*)g_w1h;
        const int n4 = NE * DM * DFF / 4;
        for (int i = gtid * 2; i < n4; i += gnth * 2) {
            float4 v0 = s[i], v1 = s[i + 1];
            uint2 H0, H1;
            H0.x = packh2(v0.x, v0.y); H0.y = packh2(v0.z, v0.w);
            H1.x = packh2(v1.x, v1.y); H1.y = packh2(v1.z, v1.w);
            p[i] = H0; p[i + 1] = H1;
        }
    }
    {
        const float4* s = (const float4*)W2;
        uint2* p = (uint2*)g_w2h;
        const int n4 = NE * DFF * DM / 4;
        for (int i = gtid * 2; i < n4; i += gnth * 2) {
            float4 v0 = s[i], v1 = s[i + 1];
            uint2 H0, H1;
            H0.x = packh2(v0.x, v0.y); H0.y = packh2(v0.z, v0.w);
            H1.x = packh2(v1.x, v1.y); H1.y = packh2(v1.z, v1.w);
            p[i] = H0; p[i + 1] = H1;
        }
    }
}

__device__ __forceinline__ void expert_base(int e, int& cnt, int& base) {
    base = 0; cnt = 0;
#pragma unroll
    for (int i = 0; i < NE; i++) {
        int c = __ldg(&g_count[i]);
        if (i < e) base += c;
        if (i == e) cnt = c;
    }
}

// ============== expert up-proj: BK=64, 2-stage, 1 sync/chunk ==============
__global__ void __launch_bounds__(256, 2) k_expert_up(const float* __restrict__ b1)
{
    const int e = blockIdx.z;
    int cnt, base;
    expert_base(e, cnt, base);
    const int m0 = blockIdx.x * 128;
    if (m0 >= cnt) return;
    const int n0 = blockIdx.y * 128;
    const float* b1e = b1 + (size_t)e * DFF;
    const size_t rowbase = (size_t)base + m0;

    extern __shared__ __align__(16) char dsm[];
    const uint32_t smb = smem_u32(dsm);
    __shared__ int rowidx[128];

    const int tid = threadIdx.x;
    const int wid = tid >> 5, lane = tid & 31;
    const int mw = (wid & 3) * 32, nw = (wid >> 2) * 64;

    if (tid < 128)
        rowidx[tid] = (m0 + tid < cnt) ? g_list[e * T_TOK + m0 + tid] : -1;
    __syncthreads();

    const __half* srcA[4];
    bool okA[4];
    uint32_t dstA[4];
#pragma unroll
    for (int i = 0; i < 4; i++) {
        int it = tid + i * 256;
        int r = it >> 3, q = it & 7;
        int gr = rowidx[r];
        okA[i] = (gr >= 0);
        srcA[i] = g_xh0 + (size_t)(okA[i] ? gr : 0) * DM + q * 8;
        dstA[i] = (uint32_t)(r * 144 + q * 16);
    }
    const __half* srcB[4];
    uint32_t dstB[4];
#pragma unroll
    for (int i = 0; i < 4; i++) {
        int it = tid + i * 256;
        int k = it >> 4, c = it & 15;
        srcB[i] = g_w1h + (size_t)e * DM * DFF + (size_t)k * DFF + n0 + c * 8;
        dstB[i] = (uint32_t)(k * 272 + c * 16);
    }

    float acc[2][8][4];
#pragma unroll
    for (int x = 0; x < 2; x++)
#pragma unroll
        for (int y = 0; y < 8; y++)
#pragma unroll
            for (int zz = 0; zz < 4; zz++) acc[x][y][zz] = 0.f;

#pragma unroll
    for (int i = 0; i < 4; i++) {
        cp16(smb + dstA[i], srcA[i], okA[i]);
        cp16(smb + E_OFFB + dstB[i], srcB[i], true);
    }
    CP_COMMIT();

    const int NK = DM / EBK;  // 8
    for (int c = 0; c < NK; c++) {
        const int s = c & 1;
        cp_wait<0>();
        __syncthreads();
        if (c + 1 < NK) {
            const uint32_t nb = smb + (s ^ 1) * E_STAGE;
            const int kc = (c + 1) * EBK;
#pragma unroll
            for (int i = 0; i < 4; i++) {
                cp16(nb + dstA[i], srcA[i] + kc, okA[i]);
                cp16(nb + E_OFFB + dstB[i], srcB[i] + (size_t)kc * DFF, true);
            }
            CP_COMMIT();
        }
        chunk1h64(smb + s * E_STAGE, mw, nw, lane, acc);
    }

#pragma unroll
    for (int mt = 0; mt < 2; mt++) {
        int lr0 = mw + mt * 16 + (lane >> 2);
        int lr1 = lr0 + 8;
        bool ok0 = (m0 + lr0 < cnt), ok1 = (m0 + lr1 < cnt);
        size_t row0 = rowbase + lr0, row1 = rowbase + lr1;
#pragma unroll
        for (int nt = 0; nt < 8; nt++) {
            int c = nw + nt * 8 + (lane & 3) * 2;
            float z0 = __ldg(&b1e[n0 + c]), z1 = __ldg(&b1e[n0 + c + 1]);
            if (ok0) {
                float v0 = fmaxf(acc[mt][nt][0] + z0, 0.f);
                float v1 = fmaxf(acc[mt][nt][1] + z1, 0.f);
                *(uint32_t*)(g_hid0 + row0 * DFF + n0 + c) = packh2(v0, v1);
            }
            if (ok1) {
                float v0 = fmaxf(acc[mt][nt][2] + z0, 0.f);
                float v1 = fmaxf(acc[mt][nt][3] + z1, 0.f);
                *(uint32_t*)(g_hid0 + row1 * DFF + n0 + c) = packh2(v0, v1);
            }
        }
    }
}

// ============== expert down-proj: split-K=2, non-atomic partials ==============
__global__ void __launch_bounds__(256, 2) k_expert_down()
{
    const int e = blockIdx.z;
    int cnt, base;
    expert_base(e, cnt, base);
    const int m0 = blockIdx.x * 128;
    if (m0 >= cnt) return;
    const int n0 = (blockIdx.y & 3) * 128;
    const int kz = blockIdx.y >> 2;
    const int kbase = kz * KSEG;
    const size_t rowbase = (size_t)base + m0;
    float* part = g_part + (size_t)kz * ROWS2 * DM;

    extern __shared__ __align__(16) char dsm[];
    const uint32_t smb = smem_u32(dsm);

    const int tid = threadIdx.x;
    const int wid = tid >> 5, lane = tid & 31;
    const int mw = (wid & 3) * 32, nw = (wid >> 2) * 64;

    const __half* srcA[4];
    bool okA[4];
    uint32_t dstA[4];
#pragma unroll
    for (int i = 0; i < 4; i++) {
        int it = tid + i * 256;
        int r = it >> 3, q = it & 7;
        okA[i] = (m0 + r < cnt);
        srcA[i] = g_hid0 + (okA[i] ? (rowbase + r) : 0) * DFF + kbase + q * 8;
        dstA[i] = (uint32_t)(r * 144 + q * 16);
    }
    const __half* srcB[4];
    uint32_t dstB[4];
#pragma unroll
    for (int i = 0; i < 4; i++) {
        int it = tid + i * 256;
        int k = it >> 4, c = it & 15;
        srcB[i] = g_w2h + (size_t)e * DFF * DM + (size_t)(kbase + k) * DM + n0 + c * 8;
        dstB[i] = (uint32_t)(k * 272 + c * 16);
    }

    float acc[2][8][4];
#pragma unroll
    for (int x = 0; x < 2; x++)
#pragma unroll
        for (int y = 0; y < 8; y++)
#pragma unroll
            for (int zz = 0; zz < 4; zz++) acc[x][y][zz] = 0.f;

#pragma unroll
    for (int i = 0; i < 4; i++) {
        cp16(smb + dstA[i], srcA[i], okA[i]);
        cp16(smb + E_OFFB + dstB[i], srcB[i], true);
    }
    CP_COMMIT();

    const int NK = KSEG / EBK;  // 16
    for (int c = 0; c < NK; c++) {
        const int s = c & 1;
        cp_wait<0>();
        __syncthreads();
        if (c + 1 < NK) {
            const uint32_t nb = smb + (s ^ 1) * E_STAGE;
            const int kc = (c + 1) * EBK;
#pragma unroll
            for (int i = 0; i < 4; i++) {
                cp16(nb + dstA[i], srcA[i] + kc, okA[i]);
                cp16(nb + E_OFFB + dstB[i], srcB[i] + (size_t)kc * DM, true);
            }
            CP_COMMIT();
        }
        chunk1h64(smb + s * E_STAGE, mw, nw, lane, acc);
    }

#pragma unroll
    for (int mt = 0; mt < 2; mt++) {
        int lr0 = mw + mt * 16 + (lane >> 2);
        int lr1 = lr0 + 8;
        bool ok0 = (m0 + lr0 < cnt), ok1 = (m0 + lr1 < cnt);
        size_t row0 = rowbase + lr0, row1 = rowbase + lr1;
#pragma unroll
        for (int nt = 0; nt < 8; nt++) {
            int c = nw + nt * 8 + (lane & 3) * 2;
            if (ok0)
                *(float2*)&part[row0 * DM + n0 + c] =
                    make_float2(acc[mt][nt][0], acc[mt][nt][1]);
            if (ok1)
                *(float2*)&part[row1 * DM + n0 + c] =
                    make_float2(acc[mt][nt][2], acc[mt][nt][3]);
        }
    }
}

// ============== combine ==============
__global__ void __launch_bounds__(128) k_combine(
    const float* __restrict__ b2, float* __restrict__ out)
{
    const int t = blockIdx.x;
    const int tid = threadIdx.x;
    __shared__ int sbase[NE];
    __shared__ int4 sslot;
    if (tid < NE) {
        int b = 0;
        for (int i = 0; i < tid; i++) b += __ldg(&g_count[i]);
        sbase[tid] = b;
    }
    if (tid == 0) sslot = g_slot[t];
    __syncthreads();

    const int e0 = sslot.x, pos0 = sslot.y, e1 = sslot.z, pos1 = sslot.w;
    const size_t r0 = (size_t)sbase[e0] + pos0;
    const size_t r1 = (size_t)sbase[e1] + pos1;
    const float w0 = __ldg(&g_wt[e0 * T_TOK + pos0]);
    const float w1 = __ldg(&g_wt[e1 * T_TOK + pos1]);
    const size_t PL = (size_t)ROWS2 * DM;

    const float4* p0a = (const float4*)(g_part + r0 * DM);
    const float4* p0b = (const float4*)(g_part + PL + r0 * DM);
    const float4* p1a = (const float4*)(g_part + r1 * DM);
    const float4* p1b = (const float4*)(g_part + PL + r1 * DM);
    const float4* bz0 = (const float4*)(b2 + (size_t)e0 * DM);
    const float4* bz1 = (const float4*)(b2 + (size_t)e1 * DM);
    float4* o = (float4*)(out + (size_t)t * DM);

    for (int c = tid; c < DM / 4; c += 128) {
        float4 a0 = p0a[c], a1 = p0b[c], z0 = bz0[c];
        float4 d0 = p1a[c], d1 = p1b[c], z1 = bz1[c];
        float4 r;
        r.x = w0 * (a0.x + a1.x + z0.x) + w1 * (d0.x + d1.x + z1.x);
        r.y = w0 * (a0.y + a1.y + z0.y) + w1 * (d0.y + d1.y + z1.y);
        r.z = w0 * (a0.z + a1.z + z0.z) + w1 * (d0.z + d1.z + z1.z);
        r.w = w0 * (a0.w + a1.w + z0.w) + w1 * (d0.w + d1.w + z1.w);
        o[c] = r;
    }
}

// ---------------- host launcher (single stream) ----------------
extern "C" void kernel_launch(void* const* d_in, const int* in_sizes, int n_in,
                              void* d_out, int out_size) {
    const float* x      = (const float*)d_in[0];
    const float* h_prev = (const float*)d_in[1];
    const float* Wp     = (const float*)d_in[2];
    const float* bp     = (const float*)d_in[3];
    const float* W_ih   = (const float*)d_in[4];
    const float* W_hh   = (const float*)d_in[5];
    const float* b_ih   = (const float*)d_in[6];
    const float* b_hh   = (const float*)d_in[7];
    const float* Wr     = (const float*)d_in[8];
    const float* br     = (const float*)d_in[9];
    const float* W1     = (const float*)d_in[10];
    const float* b1     = (const float*)d_in[11];
    const float* W2     = (const float*)d_in[12];
    const float* b2     = (const float*)d_in[13];

    float* out   = (float*)d_out;
    float* h_out = out + OUT_ELEMS;

    cudaFuncSetAttribute(k_rgemm,
                         cudaFuncAttributeMaxDynamicSharedMemorySize, R_DYN);
    cudaFuncSetAttribute(k_expert_up,
                         cudaFuncAttributeMaxDynamicSharedMemorySize, E_DYN);
    cudaFuncSetAttribute(k_expert_down,
                         cudaFuncAttributeMaxDynamicSharedMemorySize, E_DYN);

    k_prep<<<1024, 256>>>(x, h_prev, W_ih, b_ih, Wp, bp, W_hh);
    k_rgemm<<<dim3(3, 64, 2), 256, R_DYN>>>(b_hh);
    k_gru_route<<<T_TOK, 128>>>(h_prev, Wr, br, h_out, W1, W2);
    k_expert_up<<<dim3(T_TOK / 128, DFF / 128, NE), 256, E_DYN>>>(b1);
    k_expert_down<<<dim3(T_TOK / 128, (DM / 128) * KSPLIT, NE), 256, E_DYN>>>();
    k_combine<<<T_TOK, 128>>>(b2, out);
}